// round 1
// baseline (speedup 1.0000x reference)
#include <cuda_runtime.h>
#include <cstdint>

// Problem constants (static graph dims from reference)
#define BATCH   16384
#define IN_DIM  512
#define NH      128
#define NO      256
#define SRCW    (IN_DIM + NH)   // 640
#define TB      16              // batch rows per block
#define NTHREADS 256
#define BG      (TB / 4)        // batch groups of 4

__device__ __forceinline__ int lower_bound_i(const int* __restrict__ r, int n, int v) {
    int lo = 0, hi = n;
    while (lo < hi) {
        int m = (lo + hi) >> 1;
        if (r[m] < v) lo = m + 1; else hi = m;
    }
    return lo;
}

// act: 1 = identity, 2 = tanh, 3 = relu, 4 = sigmoid
__device__ __forceinline__ float edge_act(float z, int act) {
    float r = z;
    if (act == 2) r = tanhf(z);
    else if (act == 3) r = fmaxf(z, 0.0f);
    else if (act == 4) r = __fdividef(1.0f, 1.0f + __expf(-z));
    return r;
}

__global__ void __launch_bounds__(NTHREADS, 2)
wann_kernel(const float* __restrict__ x,
            const float* __restrict__ wh,
            const float* __restrict__ wo,
            const int* __restrict__ rows_h,
            const int* __restrict__ cols_h,
            const int* __restrict__ acts_h,
            const int* __restrict__ rows_o,
            const int* __restrict__ cols_o,
            const int* __restrict__ acts_o,
            int Eh, int Eo,
            float* __restrict__ out)
{
    extern __shared__ char smraw[];
    float* src = (float*)smraw;                        // [TB][SRCW]
    int2*  eh  = (int2*)(smraw + TB * SRCW * 4);       // [Eh]
    int2*  eo  = eh + Eh;                              // [Eo]
    int*   sh  = (int*)(eo + Eo);                      // [NH+1]
    int*   so  = sh + (NH + 1);                        // [NO+1]

    const int tid = threadIdx.x;
    const int b0  = blockIdx.x * TB;

    // ---- Stage 1: load x tile (coalesced float4), SMEM row stride = SRCW ----
    {
        const float4* xg = (const float4*)(x + (size_t)b0 * IN_DIM);
        const int nvec = TB * (IN_DIM / 4);
        for (int i = tid; i < nvec; i += NTHREADS) {
            int b = i / (IN_DIM / 4);
            int c = i - b * (IN_DIM / 4);
            *(float4*)(src + b * SRCW + c * 4) = xg[(size_t)b * (IN_DIM / 4) + c];
        }
    }

    // ---- Stage 2: stage packed edges into SMEM (L2-resident globals) ----
    for (int e = tid; e < Eh; e += NTHREADS) {
        int pk = cols_h[e] | (acts_h[e] << 10);
        eh[e] = make_int2(pk, __float_as_int(wh[e]));
    }
    for (int e = tid; e < Eo; e += NTHREADS) {
        int pk = cols_o[e] | (acts_o[e] << 10);
        eo[e] = make_int2(pk, __float_as_int(wo[e]));
    }

    // ---- Stage 3: CSR segment starts via binary search (rows are sorted) ----
    for (int i = tid; i <= NH; i += NTHREADS) sh[i] = lower_bound_i(rows_h, Eh, i);
    for (int i = tid; i <= NO; i += NTHREADS) so[i] = lower_bound_i(rows_o, Eo, i);

    __syncthreads();

    // ---- Stage 4: hidden nodes. tasks = NH * BG; lanes sweep nodes. ----
    for (int task = tid; task < NH * BG; task += NTHREADS) {
        int node = task & (NH - 1);
        int g    = task >> 7;               // NH == 128
        float* s0 = src + (g * 4 + 0) * SRCW;
        float* s1 = src + (g * 4 + 1) * SRCW;
        float* s2 = src + (g * 4 + 2) * SRCW;
        float* s3 = src + (g * 4 + 3) * SRCW;
        float a0 = 0.f, a1 = 0.f, a2 = 0.f, a3 = 0.f;
        int e1 = sh[node + 1];
        for (int e = sh[node]; e < e1; ++e) {
            int2 pk = eh[e];
            int col = pk.x & 1023;
            int act = pk.x >> 10;
            float w = __int_as_float(pk.y);
            a0 += edge_act(w * s0[col], act);
            a1 += edge_act(w * s1[col], act);
            a2 += edge_act(w * s2[col], act);
            a3 += edge_act(w * s3[col], act);
        }
        // H lives in src columns [512, 640)
        s0[IN_DIM + node] = a0;
        s1[IN_DIM + node] = a1;
        s2[IN_DIM + node] = a2;
        s3[IN_DIM + node] = a3;
    }

    __syncthreads();

    // ---- Stage 5: output nodes. tasks = NO * BG; coalesced store. ----
    for (int task = tid; task < NO * BG; task += NTHREADS) {
        int node = task & (NO - 1);
        int g    = task >> 8;               // NO == 256
        float* s0 = src + (g * 4 + 0) * SRCW;
        float* s1 = src + (g * 4 + 1) * SRCW;
        float* s2 = src + (g * 4 + 2) * SRCW;
        float* s3 = src + (g * 4 + 3) * SRCW;
        float a0 = 0.f, a1 = 0.f, a2 = 0.f, a3 = 0.f;
        int e1 = so[node + 1];
        for (int e = so[node]; e < e1; ++e) {
            int2 pk = eo[e];
            int col = pk.x & 1023;
            int act = pk.x >> 10;
            float w = __int_as_float(pk.y);
            a0 += edge_act(w * s0[col], act);
            a1 += edge_act(w * s1[col], act);
            a2 += edge_act(w * s2[col], act);
            a3 += edge_act(w * s3[col], act);
        }
        int bb = b0 + g * 4;
        out[(size_t)(bb + 0) * NO + node] = tanhf(a0);
        out[(size_t)(bb + 1) * NO + node] = tanhf(a1);
        out[(size_t)(bb + 2) * NO + node] = tanhf(a2);
        out[(size_t)(bb + 3) * NO + node] = tanhf(a3);
    }
}

extern "C" void kernel_launch(void* const* d_in, const int* in_sizes, int n_in,
                              void* d_out, int out_size)
{
    const float* x      = (const float*)d_in[0];
    const float* wh     = (const float*)d_in[1];
    const float* wo     = (const float*)d_in[2];
    const int*   rows_h = (const int*)d_in[3];
    const int*   cols_h = (const int*)d_in[4];
    const int*   acts_h = (const int*)d_in[5];
    const int*   rows_o = (const int*)d_in[6];
    const int*   cols_o = (const int*)d_in[7];
    const int*   acts_o = (const int*)d_in[8];
    float* out = (float*)d_out;

    int Eh = in_sizes[1];
    int Eo = in_sizes[2];

    size_t smem = (size_t)TB * SRCW * 4        // src tile
                + (size_t)(Eh + Eo) * 8        // packed edges
                + (size_t)(NH + 1 + NO + 1) * 4; // segment offsets

    cudaFuncSetAttribute(wann_kernel, cudaFuncAttributeMaxDynamicSharedMemorySize,
                         (int)(smem + 1024));

    dim3 grid(BATCH / TB);
    dim3 block(NTHREADS);
    wann_kernel<<<grid, block, smem>>>(x, wh, wo,
                                       rows_h, cols_h, acts_h,
                                       rows_o, cols_o, acts_o,
                                       Eh, Eo, out);
}

// round 2
// speedup vs baseline: 3.6515x; 3.6515x over previous
#include <cuda_runtime.h>
#include <cstdint>

#define BATCH    16384
#define IN_DIM   512
#define NH       128
#define NO       256
#define SRCW     (IN_DIM + NH)     // 640 source columns (x + H)
#define TB       64                // batch rows per tile (2 per lane)
#define NTHREADS 1024
#define NWARPS   32
#define GRID     128
#define TILES_PER_BLOCK (BATCH / TB / GRID)   // 2

// src layout: element (col, b) lives at float index
//   2*( col*32 + ((b>>1) ^ (col & 31)) ) + (b & 1)
// Read in main loop: lane p reads pair (b=2p, 2p+1): one conflict-free LDS.64.

__device__ __forceinline__ float tanha(float z) {
    float r;
    asm("tanh.approx.f32 %0, %1;" : "=f"(r) : "f"(z));
    return r;
}

__device__ __forceinline__ int lower_bound_i(const int* __restrict__ r, int n, int v) {
    int lo = 0, hi = n;
    while (lo < hi) {
        int m = (lo + hi) >> 1;
        if (r[m] < v) lo = m + 1; else hi = m;
    }
    return lo;
}

// Accumulate one edge for a pair of batch elements. act is warp-uniform.
__device__ __forceinline__ void edge_acc(float2 s, float w, int act,
                                         float& a0, float& a1) {
    float z0 = w * s.x, z1 = w * s.y;
    if (act == 2) {            // tanh
        a0 += tanha(z0); a1 += tanha(z1);
    } else if (act == 3) {     // relu
        a0 += fmaxf(z0, 0.f); a1 += fmaxf(z1, 0.f);
    } else if (act == 4) {     // sigmoid = 0.5 + 0.5*tanh(z/2)
        a0 += fmaf(0.5f, tanha(0.5f * z0), 0.5f);
        a1 += fmaf(0.5f, tanha(0.5f * z1), 0.5f);
    } else {                   // identity
        a0 += z0; a1 += z1;
    }
}

__global__ void __launch_bounds__(NTHREADS, 1)
wann_kernel(const float* __restrict__ x,
            const float* __restrict__ wh,
            const float* __restrict__ wo,
            const int* __restrict__ rows_h,
            const int* __restrict__ cols_h,
            const int* __restrict__ acts_h,
            const int* __restrict__ rows_o,
            const int* __restrict__ cols_o,
            const int* __restrict__ acts_o,
            int Eh, int Eo,
            float* __restrict__ out)
{
    extern __shared__ char sm[];
    float*  src = (float*)sm;                                   // 640*64 floats
    float2* buf = (float2*)(sm + SRCW * TB * 4);                // 32*33 float2
    int2*   eh  = (int2*)(sm + SRCW * TB * 4 + 32 * 33 * 8);    // [Eh]
    int2*   eo  = eh + Eh;                                      // [Eo]
    int*    sh  = (int*)(eo + Eo);                              // [NH+1]
    int*    so  = sh + (NH + 1);                                // [NO+1]

    const int tid  = threadIdx.x;
    const int wid  = tid >> 5;
    const int lane = tid & 31;

    // ---- Once per block: stage packed edges + CSR offsets ----
    for (int e = tid; e < Eh; e += NTHREADS)
        eh[e] = make_int2(cols_h[e] | (acts_h[e] << 10), __float_as_int(wh[e]));
    for (int e = tid; e < Eo; e += NTHREADS)
        eo[e] = make_int2(cols_o[e] | (acts_o[e] << 10), __float_as_int(wo[e]));
    for (int i = tid; i <= NH; i += NTHREADS) sh[i] = lower_bound_i(rows_h, Eh, i);
    for (int i = tid; i <= NO; i += NTHREADS) so[i] = lower_bound_i(rows_o, Eo, i);
    __syncthreads();

    for (int t = 0; t < TILES_PER_BLOCK; ++t) {
        const int tile = blockIdx.x * TILES_PER_BLOCK + t;
        const int b0t  = tile * TB;

        // ---- Stage x tile into swizzled transposed SMEM ----
        // Warp-iter: 16 col-chunks(32 cols) x 16 b-chunks(4 rows) = 256 iters.
        // Lane: sub = lane&7 picks col quad, bq = lane>>3 picks batch row.
        {
            const int sub = lane & 7, bq = lane >> 3;
            for (int it = wid; it < 256; it += NWARPS) {
                const int cchunk = it & 15;
                const int bchunk = it >> 4;
                const int b = bchunk * 4 + bq;
                const int c = cchunk * 32 + sub * 4;
                float4 v = *(const float4*)(x + (size_t)(b0t + b) * IN_DIM + c);
                #pragma unroll
                for (int j = 0; j < 4; ++j) {
                    const int cc = c + j;
                    const int g = cc * 32 + ((b >> 1) ^ (cc & 31));
                    float val = (j == 0) ? v.x : (j == 1) ? v.y : (j == 2) ? v.z : v.w;
                    src[2 * g + (b & 1)] = val;
                }
            }
        }
        __syncthreads();

        // ---- Hidden phase: warp = node, lanes = batch pairs ----
        for (int node = wid; node < NH; node += NWARPS) {
            float a0 = 0.f, a1 = 0.f;
            const int e1 = sh[node + 1];
            for (int e = sh[node]; e < e1; ++e) {
                int2 pk = eh[e];
                int col = pk.x & 1023;
                int act = pk.x >> 10;
                float w = __int_as_float(pk.y);
                int g = col * 32 + (lane ^ (col & 31));
                float2 s = *(const float2*)(src + 2 * g);
                edge_acc(s, w, act, a0, a1);
            }
            // H stored at column IN_DIM + node
            int hc = IN_DIM + node;
            int g = hc * 32 + (lane ^ (hc & 31));
            *(float2*)(src + 2 * g) = make_float2(a0, a1);
        }
        __syncthreads();

        // ---- Output phase: 8 chunks of 32 nodes; transpose via buf ----
        for (int ch = 0; ch < NO / NWARPS; ++ch) {
            const int node = ch * NWARPS + wid;
            float a0 = 0.f, a1 = 0.f;
            const int e1 = so[node + 1];
            for (int e = so[node]; e < e1; ++e) {
                int2 pk = eo[e];
                int col = pk.x & 1023;
                int act = pk.x >> 10;
                float w = __int_as_float(pk.y);
                int g = col * 32 + (lane ^ (col & 31));
                float2 s = *(const float2*)(src + 2 * g);
                edge_acc(s, w, act, a0, a1);
            }
            buf[wid * 33 + lane] = make_float2(a0, a1);
            __syncthreads();

            // Coalesced write: warp handles batch rows wid and wid+32
            #pragma unroll
            for (int rr = 0; rr < 2; ++rr) {
                const int rb = wid + rr * 32;
                float2 v = buf[lane * 33 + (rb >> 1)];
                float val = (rb & 1) ? v.y : v.x;
                out[(size_t)(b0t + rb) * NO + ch * NWARPS + lane] = tanha(val);
            }
            __syncthreads();
        }
    }
}

extern "C" void kernel_launch(void* const* d_in, const int* in_sizes, int n_in,
                              void* d_out, int out_size)
{
    const float* x      = (const float*)d_in[0];
    const float* wh     = (const float*)d_in[1];
    const float* wo     = (const float*)d_in[2];
    const int*   rows_h = (const int*)d_in[3];
    const int*   cols_h = (const int*)d_in[4];
    const int*   acts_h = (const int*)d_in[5];
    const int*   rows_o = (const int*)d_in[6];
    const int*   cols_o = (const int*)d_in[7];
    const int*   acts_o = (const int*)d_in[8];
    float* out = (float*)d_out;

    const int Eh = in_sizes[1];
    const int Eo = in_sizes[2];

    size_t smem = (size_t)SRCW * TB * 4          // src (swizzled transposed tile)
                + (size_t)32 * 33 * 8            // output transpose buffer
                + (size_t)(Eh + Eo) * 8          // packed edges
                + (size_t)(NH + 1 + NO + 1) * 4; // CSR offsets

    cudaFuncSetAttribute(wann_kernel, cudaFuncAttributeMaxDynamicSharedMemorySize,
                         (int)smem);

    wann_kernel<<<GRID, NTHREADS, smem>>>(x, wh, wo,
                                          rows_h, cols_h, acts_h,
                                          rows_o, cols_o, acts_o,
                                          Eh, Eo, out);
}

// round 3
// speedup vs baseline: 4.0990x; 1.1226x over previous
#include <cuda_runtime.h>
#include <cstdint>

#define BATCH    16384
#define IN_DIM   512
#define NH       128
#define NO       256
#define SRCW     (IN_DIM + NH)     // 640
#define TB       64                // batch rows per tile (float2 per lane)
#define NTHREADS 1024
#define NWARPS   32
#define MAXE     16384

// Persistent scratch written by prep kernels each launch (deterministic).
__device__ int2 g_edges[MAXE];          // packed (q, w) sorted by (node, act)
__device__ int  g_offh[NH * 4 + 1];     // hidden per-node per-act boundaries
__device__ int  g_offo[NO * 4 + 1];     // output per-node per-act boundaries (absolute)
__device__ int  g_hsched[NH];           // serpentine LPT schedule
__device__ int  g_osched[NO];

__device__ __forceinline__ float tanha(float z) {
    float r;
    asm("tanh.approx.f32 %0, %1;" : "=f"(r) : "f"(z));
    return r;
}

__device__ __forceinline__ int lower_bound_i(const int* __restrict__ r, int n, int v) {
    int lo = 0, hi = n;
    while (lo < hi) {
        int m = (lo + hi) >> 1;
        if (r[m] < v) lo = m + 1; else hi = m;
    }
    return lo;
}

// ---------------- Prep 1: counting-sort edges by (node, act), pack address word ----
// q = col*256 | ((col&31)<<3)  ->  per-lane smem byte addr = q ^ (lane<<3)
__global__ void prep_reorder(const int* __restrict__ rows_h, const int* __restrict__ cols_h,
                             const int* __restrict__ acts_h, const float* __restrict__ wh,
                             const int* __restrict__ rows_o, const int* __restrict__ cols_o,
                             const int* __restrict__ acts_o, const float* __restrict__ wo,
                             int Eh, int Eo)
{
    const int gw   = blockIdx.x * (blockDim.x >> 5) + (threadIdx.x >> 5);
    const int lane = threadIdx.x & 31;

    const int* rows; const int* cols; const int* acts; const float* wp;
    int E, n, obase, ooff; int* offp;
    if (gw < NH) {
        rows = rows_h; cols = cols_h; acts = acts_h; wp = wh;
        E = Eh; n = gw; obase = 0; offp = g_offh; ooff = 0;
    } else if (gw < NH + NO) {
        rows = rows_o; cols = cols_o; acts = acts_o; wp = wo;
        E = Eo; n = gw - NH; obase = Eh; offp = g_offo; ooff = 0;
    } else return;

    const int s = lower_bound_i(rows, E, n);
    const int e = lower_bound_i(rows, E, n + 1);
    int base = obase + s;

    #pragma unroll
    for (int a = 1; a <= 4; ++a) {
        if (lane == 0) offp[n * 4 + (a - 1)] = base;
        for (int c = s; c < e; c += 32) {
            const int idx = c + lane;
            const int act = (idx < e) ? acts[idx] : 0;
            const unsigned m = __ballot_sync(0xffffffffu, act == a);
            if (act == a) {
                const int r   = __popc(m & ((1u << lane) - 1));
                const int col = cols[idx];
                float w = wp[idx];
                if (a == 4) w *= 0.5f;      // sigmoid: 0.5+0.5*tanh(0.5*w*s)
                g_edges[base + r] = make_int2(col * 256 | ((col & 31) << 3),
                                              __float_as_int(w));
            }
            base += __popc(m);
        }
    }
    if (lane == 0) {
        if (gw == NH - 1)      g_offh[NH * 4] = e;          // = Eh
        if (gw == NH + NO - 1) g_offo[NO * 4] = Eh + e;     // = Eh+Eo
    }
}

// ---------------- Prep 2: LPT serpentine schedules (rank-sort by edge count) -------
__global__ void prep_sched()
{
    const int i = threadIdx.x;
    if (i < NH) {
        const int cnt = g_offh[(i + 1) * 4] - g_offh[i * 4];
        int rank = 0;
        for (int j = 0; j < NH; ++j) {
            const int cj = g_offh[(j + 1) * 4] - g_offh[j * 4];
            rank += (cj > cnt) || (cj == cnt && j < i);
        }
        const int r = rank >> 5;
        int w = rank & 31;
        if (r & 1) w = 31 - w;
        g_hsched[r * 32 + w] = i;
    } else if (i < NH + NO) {
        const int m = i - NH;
        const int cnt = g_offo[(m + 1) * 4] - g_offo[m * 4];
        int rank = 0;
        for (int j = 0; j < NO; ++j) {
            const int cj = g_offo[(j + 1) * 4] - g_offo[j * 4];
            rank += (cj > cnt) || (cj == cnt && j < m);
        }
        const int r = rank >> 5;
        int w = rank & 31;
        if (r & 1) w = 31 - w;
        g_osched[r * 32 + w] = m;
    }
}

// ---------------- Main kernel ------------------------------------------------------
// Per-edge segments (act-uniform, branch-free):
//   identity: acc += w*s            tanh: acc += tanha(w*s)
//   relu:     acc += max(w*s,0)     sigm: acc += 0.5*tanha(w*s) (+0.5 folded in bias)
#define EDGE_LOOP(E0, E1, BODY)                                              \
    _Pragma("unroll 4")                                                      \
    for (int e = (E0); e < (E1); ++e) {                                      \
        const int2 ed = __ldg(&g_edges[e]);                                  \
        const float2 s = *(const float2*)(srcb + (ed.x ^ lane8));            \
        const float w = __int_as_float(ed.y);                                \
        BODY                                                                 \
    }

__global__ void __launch_bounds__(NTHREADS, 1)
wann_main(const float* __restrict__ x, float* __restrict__ out)
{
    extern __shared__ char sm[];
    float*  src    = (float*)sm;                                   // 640*64 floats
    float2* buf    = (float2*)(sm + SRCW * TB * 4);                // 32*33 float2
    int*    s_offh = (int*)(sm + SRCW * TB * 4 + 32 * 33 * 8);     // 513
    int*    s_offo = s_offh + (NH * 4 + 1);                        // 1025
    int*    s_hs   = s_offo + (NO * 4 + 1);                        // 128
    int*    s_os   = s_hs + NH;                                    // 256

    const int tid = threadIdx.x, wid = tid >> 5, lane = tid & 31;
    const int lane8 = lane << 3;
    const char* srcb = (const char*)sm;

    for (int i = tid; i < NH * 4 + 1; i += NTHREADS) s_offh[i] = g_offh[i];
    for (int i = tid; i < NO * 4 + 1; i += NTHREADS) s_offo[i] = g_offo[i];
    for (int i = tid; i < NH; i += NTHREADS) s_hs[i] = g_hsched[i];
    for (int i = tid; i < NO; i += NTHREADS) s_os[i] = g_osched[i];

    const int b0t = blockIdx.x * TB;

    // ---- Stage x tile into swizzled transposed SMEM (conflict-free) ----
    {
        const int sub = lane & 7, bq = lane >> 3;
        for (int it = wid; it < 256; it += NWARPS) {
            const int cchunk = it & 15;
            const int bchunk = it >> 4;
            const int b = bchunk * 4 + bq;
            const int c = cchunk * 32 + sub * 4;
            const float4 v = *(const float4*)(x + (size_t)(b0t + b) * IN_DIM + c);
            #pragma unroll
            for (int j = 0; j < 4; ++j) {
                const int cc = c + j;
                const int g = cc * 32 + ((b >> 1) ^ (cc & 31));
                const float val = (j == 0) ? v.x : (j == 1) ? v.y : (j == 2) ? v.z : v.w;
                src[2 * g + (b & 1)] = val;
            }
        }
    }
    __syncthreads();

    // ---- Hidden phase: warp=node via serpentine schedule, branch-free segments ----
    #pragma unroll
    for (int rr = 0; rr < NH / NWARPS; ++rr) {
        const int node = s_hs[rr * NWARPS + wid];
        const int* ofs = s_offh + node * 4;
        const int e0 = ofs[0], e1 = ofs[1], e2 = ofs[2], e3 = ofs[3], e4 = ofs[4];
        const float bias = 0.5f * (float)(e4 - e3);
        float a0 = bias, a1 = bias;
        EDGE_LOOP(e0, e1, { a0 = fmaf(w, s.x, a0); a1 = fmaf(w, s.y, a1); })
        EDGE_LOOP(e1, e2, { a0 += tanha(w * s.x); a1 += tanha(w * s.y); })
        EDGE_LOOP(e2, e3, { a0 += fmaxf(w * s.x, 0.f); a1 += fmaxf(w * s.y, 0.f); })
        EDGE_LOOP(e3, e4, { a0 = fmaf(0.5f, tanha(w * s.x), a0);
                            a1 = fmaf(0.5f, tanha(w * s.y), a1); })
        const int hc = IN_DIM + node;
        const int qh = hc * 256 | ((hc & 31) << 3);
        *(float2*)((char*)sm + (qh ^ lane8)) = make_float2(a0, a1);
    }
    __syncthreads();

    // ---- Output phase: compute all 8 nodes/warp into registers (one sync) ----
    float2 res[NO / NWARPS];
    int    onode[NO / NWARPS];
    #pragma unroll
    for (int rr = 0; rr < NO / NWARPS; ++rr) {
        const int node = s_os[rr * NWARPS + wid];
        onode[rr] = node;
        const int* ofs = s_offo + node * 4;
        const int e0 = ofs[0], e1 = ofs[1], e2 = ofs[2], e3 = ofs[3], e4 = ofs[4];
        const float bias = 0.5f * (float)(e4 - e3);
        float a0 = bias, a1 = bias;
        EDGE_LOOP(e0, e1, { a0 = fmaf(w, s.x, a0); a1 = fmaf(w, s.y, a1); })
        EDGE_LOOP(e1, e2, { a0 += tanha(w * s.x); a1 += tanha(w * s.y); })
        EDGE_LOOP(e2, e3, { a0 += fmaxf(w * s.x, 0.f); a1 += fmaxf(w * s.y, 0.f); })
        EDGE_LOOP(e3, e4, { a0 = fmaf(0.5f, tanha(w * s.x), a0);
                            a1 = fmaf(0.5f, tanha(w * s.y), a1); })
        res[rr] = make_float2(tanha(a0), tanha(a1));
    }

    // ---- Write rounds: transpose via buf, uniform work per round ----
    #pragma unroll
    for (int ch = 0; ch < NO / 32; ++ch) {
        __syncthreads();
        #pragma unroll
        for (int rr = 0; rr < NO / NWARPS; ++rr)
            if ((onode[rr] >> 5) == ch)
                buf[(onode[rr] & 31) * 33 + lane] = res[rr];
        __syncthreads();
        #pragma unroll
        for (int r2 = 0; r2 < 2; ++r2) {
            const int rb = wid + r2 * 32;
            const float2 v = buf[lane * 33 + (rb >> 1)];
            out[(size_t)(b0t + rb) * NO + ch * 32 + lane] = (rb & 1) ? v.y : v.x;
        }
    }
}

extern "C" void kernel_launch(void* const* d_in, const int* in_sizes, int n_in,
                              void* d_out, int out_size)
{
    const float* x      = (const float*)d_in[0];
    const float* wh     = (const float*)d_in[1];
    const float* wo     = (const float*)d_in[2];
    const int*   rows_h = (const int*)d_in[3];
    const int*   cols_h = (const int*)d_in[4];
    const int*   acts_h = (const int*)d_in[5];
    const int*   rows_o = (const int*)d_in[6];
    const int*   cols_o = (const int*)d_in[7];
    const int*   acts_o = (const int*)d_in[8];
    float* out = (float*)d_out;

    const int Eh = in_sizes[1];
    const int Eo = in_sizes[2];

    prep_reorder<<<12, 1024>>>(rows_h, cols_h, acts_h, wh,
                               rows_o, cols_o, acts_o, wo, Eh, Eo);
    prep_sched<<<1, NH + NO>>>();

    const size_t smem = (size_t)SRCW * TB * 4        // src tile (swizzled)
                      + (size_t)32 * 33 * 8          // transpose buffer
                      + (size_t)(NH * 4 + 1 + NO * 4 + 1 + NH + NO) * 4;

    cudaFuncSetAttribute(wann_main, cudaFuncAttributeMaxDynamicSharedMemorySize,
                         (int)smem);
    wann_main<<<BATCH / TB, NTHREADS, smem>>>(x, out);
}

// round 4
// speedup vs baseline: 4.3865x; 1.0701x over previous
#include <cuda_runtime.h>
#include <cstdint>

#define BATCH    16384
#define IN_DIM   512
#define NH       128
#define NO       256
#define NNODES   (NH + NO)         // 384
#define SRCW     (IN_DIM + NH)     // 640
#define TB       64                // batch rows per tile (float2 per lane)
#define NTHREADS 1024
#define NWARPS   32
#define MAXE     16384

// Persistent scratch rebuilt by prep each launch (deterministic).
__device__ int2 g_edges[MAXE];       // packed (q, w), sorted by (node, act)
__device__ int4 g_infoA[NNODES];     // per schedule slot: e0,e1,e2,e3
__device__ int2 g_infoB[NNODES];     // per schedule slot: e4, node_id

__device__ __forceinline__ float tanha(float z) {
    float r;
    asm("tanh.approx.f32 %0, %1;" : "=f"(r) : "f"(z));
    return r;
}

// ================= Fused prep: histogram + scan + scatter + LPT (1 block) =========
__global__ void __launch_bounds__(1024)
prep_all(const int* __restrict__ rows_h, const int* __restrict__ cols_h,
         const int* __restrict__ acts_h, const float* __restrict__ wh,
         const int* __restrict__ rows_o, const int* __restrict__ cols_o,
         const int* __restrict__ acts_o, const float* __restrict__ wo,
         int Eh, int Eo)
{
    __shared__ int cnt[NNODES * 4];
    __shared__ int off[NNODES * 4 + 1];
    __shared__ int wsum[32];

    const int tid = threadIdx.x, lane = tid & 31, wid = tid >> 5;

    for (int i = tid; i < NNODES * 4; i += 1024) cnt[i] = 0;
    __syncthreads();

    // --- histogram over (node, act) ---
    for (int e = tid; e < Eh; e += 1024)
        atomicAdd(&cnt[rows_h[e] * 4 + acts_h[e] - 1], 1);
    for (int e = tid; e < Eo; e += 1024)
        atomicAdd(&cnt[(NH + rows_o[e]) * 4 + acts_o[e] - 1], 1);
    __syncthreads();

    // --- exclusive prefix scan over 1536 entries (48 per warp, then warp scan) ---
    if (lane == 0) {
        const int base = wid * 48;
        int run = 0;
        for (int i = 0; i < 48; ++i) { off[base + i] = run; run += cnt[base + i]; }
        wsum[wid] = run;
    }
    __syncthreads();
    if (wid == 0) {
        const int v = wsum[lane];
        int ex = v;
        #pragma unroll
        for (int d = 1; d < 32; d <<= 1) {
            const int t = __shfl_up_sync(0xffffffffu, ex, d);
            if (lane >= d) ex += t;
        }
        ex -= v;
        wsum[lane] = ex;
        if (lane == 31) off[NNODES * 4] = ex + v;
    }
    __syncthreads();
    for (int i = tid; i < NNODES * 4; i += 1024) off[i] += wsum[i / 48];
    __syncthreads();

    // --- stable scatter: warp per node, ballot compaction per act ---
    for (int n = wid; n < NNODES; n += 32) {
        const bool hid = n < NH;
        const int* cols = hid ? cols_h : cols_o;
        const int* acts = hid ? acts_h : acts_o;
        const float* wp = hid ? wh : wo;
        const int sub = hid ? 0 : Eh;
        const int s = off[n * 4] - sub;
        const int e = off[(n + 1) * 4] - sub;
        int d0 = off[n * 4], d1 = off[n * 4 + 1], d2 = off[n * 4 + 2], d3 = off[n * 4 + 3];
        for (int c = s; c < e; c += 32) {
            const int idx = c + lane;
            const bool v = idx < e;
            const int act = v ? acts[idx] : 0;
            const int col = v ? cols[idx] : 0;
            const float w = v ? wp[idx] : 0.f;
            const int pk = col * 256 | ((col & 31) << 3);
            #pragma unroll
            for (int a = 1; a <= 4; ++a) {
                const unsigned mm = __ballot_sync(0xffffffffu, act == a);
                int& d = (a == 1) ? d0 : (a == 2) ? d1 : (a == 3) ? d2 : d3;
                if (act == a) {
                    const int r = __popc(mm & ((1u << lane) - 1));
                    const float ww = (a == 4) ? 0.5f * w : w;   // sigmoid pre-halved
                    g_edges[d + r] = make_int2(pk, __float_as_int(ww));
                }
                d += __popc(mm);
            }
        }
    }
    __syncthreads();

    // --- LPT serpentine schedule + packed per-slot node info ---
    if (tid < NNODES) {
        const int n = tid;
        const bool hid = n < NH;
        const int cn = off[(n + 1) * 4] - off[n * 4];
        const int lo = hid ? 0 : NH, hi2 = hid ? NH : NNODES;
        int rank = 0;
        for (int j = lo; j < hi2; ++j) {
            const int cj = off[(j + 1) * 4] - off[j * 4];
            rank += (cj > cn) || (cj == cn && j < n);
        }
        const int r = rank >> 5;
        int wl = rank & 31;
        if (r & 1) wl = 31 - wl;
        const int slot = (hid ? 0 : NH) + r * 32 + wl;
        g_infoA[slot] = make_int4(off[n * 4], off[n * 4 + 1], off[n * 4 + 2], off[n * 4 + 3]);
        g_infoB[slot] = make_int2(off[(n + 1) * 4], hid ? n : n - NH);
    }
}

// ================= Main kernel ====================================================
#define EDGE_LOOP(E0, E1, BODY)                                              \
    _Pragma("unroll 4")                                                      \
    for (int e = (E0); e < (E1); ++e) {                                      \
        const int2 ed = se[e];                                               \
        const float2 s = *(const float2*)(srcb + (ed.x ^ lane8));            \
        const float w = __int_as_float(ed.y);                                \
        BODY                                                                 \
    }

__global__ void __launch_bounds__(NTHREADS, 1)
wann_main(const float* __restrict__ x, float* __restrict__ out, int Etot)
{
    extern __shared__ char sm[];
    float*  src = (float*)sm;                        // [640*64] swizzled transposed
    int2*   se  = (int2*)(sm + SRCW * TB * 4);       // [Etot] packed edges
    float2* buf = (float2*)sm;                       // ALIASES src (used after compute)

    const int tid = threadIdx.x, wid = tid >> 5, lane = tid & 31;
    const int lane8 = lane << 3;
    const char* srcb = (const char*)sm;
    const int b0t = blockIdx.x * TB;

    // ---- stage edges into SMEM ----
    for (int i = tid; i < Etot; i += NTHREADS) se[i] = g_edges[i];

    // ---- stage x tile into swizzled transposed SMEM ----
    {
        const int sub = lane & 7, bq = lane >> 3;
        for (int it = wid; it < 256; it += NWARPS) {
            const int cchunk = it & 15;
            const int bchunk = it >> 4;
            const int b = bchunk * 4 + bq;
            const int c = cchunk * 32 + sub * 4;
            const float4 v = *(const float4*)(x + (size_t)(b0t + b) * IN_DIM + c);
            #pragma unroll
            for (int j = 0; j < 4; ++j) {
                const int cc = c + j;
                const int g = cc * 32 + ((b >> 1) ^ (cc & 31));
                const float val = (j == 0) ? v.x : (j == 1) ? v.y : (j == 2) ? v.z : v.w;
                src[2 * g + (b & 1)] = val;
            }
        }
    }
    __syncthreads();

    // ---- hidden phase: warp = node (LPT schedule), branch-free act segments ----
    #pragma unroll
    for (int rr = 0; rr < NH / NWARPS; ++rr) {
        const int slot = rr * NWARPS + wid;
        const int4 A  = __ldg(&g_infoA[slot]);
        const int2 Bi = __ldg(&g_infoB[slot]);
        const float bias = 0.5f * (float)(Bi.x - A.w);
        float a0 = bias, a1 = bias;
        EDGE_LOOP(A.x, A.y, { a0 = fmaf(w, s.x, a0); a1 = fmaf(w, s.y, a1); })
        EDGE_LOOP(A.y, A.z, { a0 += tanha(w * s.x); a1 += tanha(w * s.y); })
        EDGE_LOOP(A.z, A.w, { a0 += fmaxf(w * s.x, 0.f); a1 += fmaxf(w * s.y, 0.f); })
        EDGE_LOOP(A.w, Bi.x, { a0 = fmaf(0.5f, tanha(w * s.x), a0);
                               a1 = fmaf(0.5f, tanha(w * s.y), a1); })
        const int hc = IN_DIM + Bi.y;
        const int qh = hc * 256 | ((hc & 31) << 3);
        *(float2*)((char*)sm + (qh ^ lane8)) = make_float2(a0, a1);
    }
    __syncthreads();

    // ---- output phase: all 8 nodes per warp into registers ----
    float2 res[NO / NWARPS];
    int    onode[NO / NWARPS];
    #pragma unroll
    for (int rr = 0; rr < NO / NWARPS; ++rr) {
        const int slot = NH + rr * NWARPS + wid;
        const int4 A  = __ldg(&g_infoA[slot]);
        const int2 Bi = __ldg(&g_infoB[slot]);
        onode[rr] = Bi.y;
        const float bias = 0.5f * (float)(Bi.x - A.w);
        float a0 = bias, a1 = bias;
        EDGE_LOOP(A.x, A.y, { a0 = fmaf(w, s.x, a0); a1 = fmaf(w, s.y, a1); })
        EDGE_LOOP(A.y, A.z, { a0 += tanha(w * s.x); a1 += tanha(w * s.y); })
        EDGE_LOOP(A.z, A.w, { a0 += fmaxf(w * s.x, 0.f); a1 += fmaxf(w * s.y, 0.f); })
        EDGE_LOOP(A.w, Bi.x, { a0 = fmaf(0.5f, tanha(w * s.x), a0);
                               a1 = fmaf(0.5f, tanha(w * s.y), a1); })
        res[rr] = make_float2(tanha(a0), tanha(a1));
    }

    // ---- write rounds: transpose via buf (aliasing src), coalesced STG ----
    #pragma unroll
    for (int ch = 0; ch < NO / 32; ++ch) {
        __syncthreads();
        #pragma unroll
        for (int rr = 0; rr < NO / NWARPS; ++rr)
            if ((onode[rr] >> 5) == ch)
                buf[(onode[rr] & 31) * 33 + lane] = res[rr];
        __syncthreads();
        #pragma unroll
        for (int r2 = 0; r2 < 2; ++r2) {
            const int rb = wid + r2 * 32;
            const float2 v = buf[lane * 33 + (rb >> 1)];
            out[(size_t)(b0t + rb) * NO + ch * 32 + lane] = (rb & 1) ? v.y : v.x;
        }
    }
}

extern "C" void kernel_launch(void* const* d_in, const int* in_sizes, int n_in,
                              void* d_out, int out_size)
{
    const float* x      = (const float*)d_in[0];
    const float* wh     = (const float*)d_in[1];
    const float* wo     = (const float*)d_in[2];
    const int*   rows_h = (const int*)d_in[3];
    const int*   cols_h = (const int*)d_in[4];
    const int*   acts_h = (const int*)d_in[5];
    const int*   rows_o = (const int*)d_in[6];
    const int*   cols_o = (const int*)d_in[7];
    const int*   acts_o = (const int*)d_in[8];
    float* out = (float*)d_out;

    const int Eh = in_sizes[1];
    const int Eo = in_sizes[2];
    const int Etot = Eh + Eo;

    prep_all<<<1, 1024>>>(rows_h, cols_h, acts_h, wh,
                          rows_o, cols_o, acts_o, wo, Eh, Eo);

    const size_t smem = (size_t)SRCW * TB * 4 + (size_t)Etot * 8;
    cudaFuncSetAttribute(wann_main, cudaFuncAttributeMaxDynamicSharedMemorySize,
                         (int)smem);
    wann_main<<<BATCH / TB, NTHREADS, smem>>>(x, out, Etot);
}